// round 1
// baseline (speedup 1.0000x reference)
#include <cuda_runtime.h>
#include <stdint.h>

#define BATCH   16
#define NANCH   25200
#define NCLS    80
#define STRIDE  85
#define MAXC    1000
#define CONF_T  0.25f
#define IOU_T   0.45f
#define BINS    4096
#define CAP     4096   // candidate buffer for sort (power of two)

// ---------------- scratch (no allocations allowed) ----------------
__device__ float         g_scores[BATCH * NANCH];
__device__ unsigned char g_cls[BATCH * NANCH];
__device__ unsigned int  g_hist[BATCH * BINS];
__device__ unsigned int  g_selIdx[BATCH * MAXC];
__device__ unsigned int  g_selScore[BATCH * MAXC];

// ---------------- K0: zero histograms (graph replays!) ----------------
__global__ void k_zero()
{
    int t = blockIdx.x * blockDim.x + threadIdx.x;
    if (t < BATCH * BINS) g_hist[t] = 0u;
}

// ---------------- K1: warp-per-anchor score / argmax / histogram ----------------
__global__ void k_score(const float* __restrict__ pred)
{
    int gw   = (blockIdx.x * blockDim.x + threadIdx.x) >> 5;
    int lane = threadIdx.x & 31;
    if (gw >= BATCH * NANCH) return;

    const float* p = pred + (size_t)gw * STRIDE;
    // 85 channels: [x y w h obj cls0..cls79]; lane covers ch lane, lane+32, lane+64
    float v0 = __ldg(p + lane);
    float v1 = __ldg(p + 32 + lane);
    float v2 = (lane < 21) ? __ldg(p + 64 + lane) : 0.0f;

    float obj = __shfl_sync(0xffffffffu, v0, 4);

    // local best product*obj with ascending class order (strict > keeps first max)
    float bv = -1.0f;
    int   bc = 0x7fffffff;
    if (lane >= 5) { float s = __fmul_rn(v0, obj); if (s > bv) { bv = s; bc = lane - 5;  } }
    {                float s = __fmul_rn(v1, obj); if (s > bv) { bv = s; bc = lane + 27; } }
    if (lane < 21) { float s = __fmul_rn(v2, obj); if (s > bv) { bv = s; bc = lane + 59; } }

    // warp reduce: larger value wins; on exact tie, lower class index wins (jnp.argmax)
    for (int off = 16; off; off >>= 1) {
        float ov = __shfl_down_sync(0xffffffffu, bv, off);
        int   oc = __shfl_down_sync(0xffffffffu, bc, off);
        if (ov > bv || (ov == bv && oc < bc)) { bv = ov; bc = oc; }
    }

    if (lane == 0) {
        bool  valid = (obj > CONF_T) && (bv > CONF_T);
        float score = valid ? bv : -1.0f;
        g_scores[gw] = score;
        g_cls[gw]    = (unsigned char)(bc & 0xff);
        if (valid) {
            // valid score in (0.25, 1): bits in (0x3E800000, 0x3F800000) -> exact 4096 bins
            unsigned bits = __float_as_uint(bv);
            int bin = (int)(bits >> 12) - 0x3E800;
            bin = bin < 0 ? 0 : (bin > BINS - 1 ? BINS - 1 : bin);
            atomicAdd(&g_hist[(gw / NANCH) * BINS + bin], 1u);
        }
    }
}

// ---------------- K2: per-batch exact top-1000 (radix bin + bitonic) ----------------
__global__ void __launch_bounds__(1024) k_select()
{
    int b = blockIdx.x;
    int t = threadIdx.x;

    __shared__ unsigned int       sSuf[1024];
    __shared__ unsigned long long sKeys[CAP];
    __shared__ int sTq, sT, sCnt;

    // per-thread chunk of 4 bins
    unsigned int csum = g_hist[b * BINS + 4 * t + 0]
                      + g_hist[b * BINS + 4 * t + 1]
                      + g_hist[b * BINS + 4 * t + 2]
                      + g_hist[b * BINS + 4 * t + 3];
    sSuf[t] = csum;
    __syncthreads();
    // inclusive suffix scan (Hillis-Steele)
    for (int d = 1; d < 1024; d <<= 1) {
        unsigned int v = (t + d < 1024) ? sSuf[t + d] : 0u;
        __syncthreads();
        sSuf[t] += v;
        __syncthreads();
    }
    unsigned int total = sSuf[0];
    unsigned int K = total < MAXC ? total : MAXC;

    if (t == 0) { sTq = 1024; sCnt = 0; }
    __syncthreads();
    if (K > 0 && t > 0 && sSuf[t] < K && sSuf[t - 1] >= K) sTq = t;
    __syncthreads();

    if (t == 0) {
        if (K == 0) {
            sT = BINS;  // nothing qualifies
        } else {
            int chunk = sTq - 1;
            unsigned int running = (sTq < 1024) ? sSuf[sTq] : 0u;
            int T = chunk * 4;
            for (int bb = chunk * 4 + 3; bb >= chunk * 4; --bb) {
                running += g_hist[b * BINS + bb];
                if (running >= K) { T = bb; break; }
            }
            sT = T;
        }
    }
    for (int i = t; i < CAP; i += 1024) sKeys[i] = 0ull;
    __syncthreads();

    // compact candidates with bin >= T as 64-bit keys (score_bits desc, idx asc)
    int T = sT;
    for (int n = t; n < NANCH; n += 1024) {
        float sc = g_scores[b * NANCH + n];
        if (sc > 0.0f) {
            unsigned bits = __float_as_uint(sc);
            int bin = (int)(bits >> 12) - 0x3E800;
            bin = bin < 0 ? 0 : (bin > BINS - 1 ? BINS - 1 : bin);
            if (bin >= T) {
                int pos = atomicAdd(&sCnt, 1);
                if (pos < CAP)
                    sKeys[pos] = ((unsigned long long)bits << 32)
                               | (unsigned long long)(0xFFFFFFFFu - (unsigned)n);
            }
        }
    }
    __syncthreads();

    // bitonic sort, descending; padding (key=0) sinks to the bottom
    for (int k = 2; k <= CAP; k <<= 1) {
        for (int j = k >> 1; j > 0; j >>= 1) {
#pragma unroll
            for (int s = 0; s < 4; ++s) {
                int i = t + s * 1024;
                int q = i ^ j;
                if (q > i) {
                    unsigned long long a = sKeys[i], c = sKeys[q];
                    bool up = ((i & k) == 0);
                    if (up ? (a < c) : (a > c)) { sKeys[i] = c; sKeys[q] = a; }
                }
            }
            __syncthreads();
        }
    }

    if (t < MAXC) {
        unsigned long long key = sKeys[t];
        unsigned bits = (unsigned)(key >> 32);
        unsigned idx  = bits ? (0xFFFFFFFFu - (unsigned)(key & 0xFFFFFFFFu)) : 0xFFFFFFFFu;
        g_selIdx[b * MAXC + t]   = idx;
        g_selScore[b * MAXC + t] = bits;
    }
}

// ---------------- K3: per-batch greedy NMS + output ----------------
__global__ void __launch_bounds__(1024) k_nms(const float* __restrict__ pred,
                                              float* __restrict__ out)
{
    int b = blockIdx.x;
    int j = threadIdx.x;

    __shared__ float sx1[MAXC], sy1[MAXC], sx2[MAXC], sy2[MAXC], sar[MAXC];
    __shared__ int   skeep[MAXC];

    float bx1 = 0, by1 = 0, bx2 = 0, by2 = 0, conf = 0;
    float ox1 = 0, oy1 = 0, ox2 = 0, oy2 = 0, area = 0;
    int   cls = 0, myvalid = 0;

    if (j < MAXC) {
        unsigned bits = g_selScore[b * MAXC + j];
        if (bits) {
            unsigned idx = g_selIdx[b * MAXC + j];
            const float* p = pred + ((size_t)b * NANCH + idx) * STRIDE;
            float x = __ldg(p + 0), y = __ldg(p + 1);
            float w = __ldg(p + 2), h = __ldg(p + 3);
            float hw = __fmul_rn(w, 0.5f), hh = __fmul_rn(h, 0.5f);
            bx1 = __fsub_rn(x, hw); by1 = __fsub_rn(y, hh);
            bx2 = __fadd_rn(x, hw); by2 = __fadd_rn(y, hh);
            conf = __uint_as_float(bits);
            cls  = (int)g_cls[b * NANCH + idx];
            float off = __fmul_rn((float)cls, 4096.0f);  // exact (pow2)
            ox1 = __fadd_rn(bx1, off); oy1 = __fadd_rn(by1, off);
            ox2 = __fadd_rn(bx2, off); oy2 = __fadd_rn(by2, off);
            area = __fmul_rn(__fsub_rn(ox2, ox1), __fsub_rn(oy2, oy1));
            myvalid = (conf > 0.0f) ? 1 : 0;
        }
        sx1[j] = ox1; sy1[j] = oy1; sx2[j] = ox2; sy2[j] = oy2; sar[j] = area;
        skeep[j] = myvalid;
    }
    __syncthreads();

    int mykeep = myvalid;
    for (int i = 0; i < MAXC; ++i) {
        int ki = skeep[i];           // uniform: last write separated by a barrier
        if (ki) {
            if (j > i && j < MAXC && mykeep) {
                float ltx = fmaxf(sx1[i], ox1);
                float lty = fmaxf(sy1[i], oy1);
                float rbx = fminf(sx2[i], ox2);
                float rby = fminf(sy2[i], oy2);
                float ww  = fmaxf(__fsub_rn(rbx, ltx), 0.0f);
                float hh2 = fmaxf(__fsub_rn(rby, lty), 0.0f);
                float inter = __fmul_rn(ww, hh2);
                float den = __fadd_rn(__fsub_rn(__fadd_rn(sar[i], area), inter), 1e-7f);
                float iou = __fdiv_rn(inter, den);
                if (iou > IOU_T) { mykeep = 0; skeep[j] = 0; }
            }
            __syncthreads();         // only on kept iterations (no writes otherwise)
        }
    }

    if (j < MAXC) {
        float* o = out + ((size_t)b * MAXC + j) * 6;
        if (mykeep) {
            o[0] = bx1; o[1] = by1; o[2] = bx2; o[3] = by2;
            o[4] = conf; o[5] = (float)cls;
        } else {
            o[0] = 0.f; o[1] = 0.f; o[2] = 0.f; o[3] = 0.f; o[4] = 0.f; o[5] = 0.f;
        }
        out[(size_t)BATCH * MAXC * 6 + b * MAXC + j] = mykeep ? 1.0f : 0.0f;
    }
}

// ---------------- launch ----------------
extern "C" void kernel_launch(void* const* d_in, const int* in_sizes, int n_in,
                              void* d_out, int out_size)
{
    (void)in_sizes; (void)n_in; (void)out_size;
    const float* pred = (const float*)d_in[0];
    float* out = (float*)d_out;

    k_zero<<<(BATCH * BINS + 255) / 256, 256>>>();

    int totalThreads = BATCH * NANCH * 32;   // warp per anchor
    k_score<<<(totalThreads + 255) / 256, 256>>>(pred);

    k_select<<<BATCH, 1024>>>();
    k_nms<<<BATCH, 1024>>>(pred, out);
}

// round 2
// speedup vs baseline: 3.7011x; 3.7011x over previous
#include <cuda_runtime.h>
#include <stdint.h>

#define BATCH   16
#define NANCH   25200
#define NCLS    80
#define STRIDE  85
#define MAXC    1000
#define CONF_T  0.25f
#define IOU_T   0.45f
#define BINS    4096
#define CAP     4096    // candidate compaction buffer (keys)
#define KCAP    128     // max kept boxes per (batch,class)
#define CPB     8       // classes per block in k_nms (one warp each)

// ---------------- scratch (no allocations allowed) ----------------
__device__ float         g_scores[BATCH * NANCH];
__device__ unsigned char g_cls[BATCH * NANCH];
__device__ unsigned int  g_hist[BATCH * BINS];

// per-candidate (rank-ordered) data, [BATCH][MAXC]
__device__ int   g_cmeta[BATCH * MAXC];                 // class or -1
__device__ float g_ox1[BATCH * MAXC], g_oy1[BATCH * MAXC];
__device__ float g_ox2[BATCH * MAXC], g_oy2[BATCH * MAXC];
__device__ float g_oar[BATCH * MAXC];
__device__ float g_bx1[BATCH * MAXC], g_by1[BATCH * MAXC];
__device__ float g_bx2[BATCH * MAXC], g_by2[BATCH * MAXC];
__device__ float g_conf[BATCH * MAXC];

// ---------------- K0: zero histograms + output (graph replays!) ----------------
__global__ void k_zero(float* __restrict__ out, int out_size)
{
    int t = blockIdx.x * blockDim.x + threadIdx.x;
    if (t < BATCH * BINS) g_hist[t] = 0u;
    if (t < out_size) out[t] = 0.0f;
}

// ---------------- K1: warp-per-anchor score / argmax / histogram ----------------
__global__ void k_score(const float* __restrict__ pred)
{
    int gw   = (blockIdx.x * blockDim.x + threadIdx.x) >> 5;
    int lane = threadIdx.x & 31;
    if (gw >= BATCH * NANCH) return;

    const float* p = pred + (size_t)gw * STRIDE;
    float v0 = __ldg(p + lane);
    float v1 = __ldg(p + 32 + lane);
    float v2 = (lane < 21) ? __ldg(p + 64 + lane) : 0.0f;

    float obj = __shfl_sync(0xffffffffu, v0, 4);

    float bv = -1.0f;
    int   bc = 0x7fffffff;
    if (lane >= 5) { float s = __fmul_rn(v0, obj); if (s > bv) { bv = s; bc = lane - 5;  } }
    {                float s = __fmul_rn(v1, obj); if (s > bv) { bv = s; bc = lane + 27; } }
    if (lane < 21) { float s = __fmul_rn(v2, obj); if (s > bv) { bv = s; bc = lane + 59; } }

    for (int off = 16; off; off >>= 1) {
        float ov = __shfl_down_sync(0xffffffffu, bv, off);
        int   oc = __shfl_down_sync(0xffffffffu, bc, off);
        if (ov > bv || (ov == bv && oc < bc)) { bv = ov; bc = oc; }
    }

    if (lane == 0) {
        bool  valid = (obj > CONF_T) && (bv > CONF_T);
        g_scores[gw] = valid ? bv : -1.0f;
        g_cls[gw]    = (unsigned char)(bc & 0xff);
        if (valid) {
            unsigned bits = __float_as_uint(bv);
            int bin = (int)(bits >> 12) - 0x3E800;
            bin = bin < 0 ? 0 : (bin > BINS - 1 ? BINS - 1 : bin);
            atomicAdd(&g_hist[(gw / NANCH) * BINS + bin], 1u);
        }
    }
}

// ---------------- K2: per-batch exact top-1000 (radix threshold + rank-by-count)
//                  fused with candidate box/offset/area prep ----------------
__global__ void __launch_bounds__(1024) k_select(const float* __restrict__ pred)
{
    int b = blockIdx.x;
    int t = threadIdx.x;

    __shared__ unsigned int       sSuf[1024];
    __shared__ unsigned long long sKeys[CAP];
    __shared__ int sTq, sT, sCnt;

    // suffix scan over histogram (chunks of 4 bins per thread)
    unsigned int csum = g_hist[b * BINS + 4 * t + 0]
                      + g_hist[b * BINS + 4 * t + 1]
                      + g_hist[b * BINS + 4 * t + 2]
                      + g_hist[b * BINS + 4 * t + 3];
    sSuf[t] = csum;
    __syncthreads();
    for (int d = 1; d < 1024; d <<= 1) {
        unsigned int v = (t + d < 1024) ? sSuf[t + d] : 0u;
        __syncthreads();
        sSuf[t] += v;
        __syncthreads();
    }
    unsigned int total = sSuf[0];
    unsigned int K = total < MAXC ? total : MAXC;

    if (t == 0) { sTq = 1024; sCnt = 0; }
    __syncthreads();
    if (K > 0 && t > 0 && sSuf[t] < K && sSuf[t - 1] >= K) sTq = t;
    __syncthreads();

    if (t == 0) {
        if (K == 0) {
            sT = BINS;
        } else {
            int chunk = sTq - 1;
            unsigned int running = (sTq < 1024) ? sSuf[sTq] : 0u;
            int T = chunk * 4;
            for (int bb = chunk * 4 + 3; bb >= chunk * 4; --bb) {
                running += g_hist[b * BINS + bb];
                if (running >= K) { T = bb; break; }
            }
            sT = T;
        }
    }
    if (t < MAXC) g_cmeta[b * MAXC + t] = -1;   // default: no candidate
    __syncthreads();

    // compact candidates with bin >= T (unordered; order recovered by ranking)
    int T = sT;
    for (int n = t; n < NANCH; n += 1024) {
        float sc = g_scores[b * NANCH + n];
        if (sc > 0.0f) {
            unsigned bits = __float_as_uint(sc);
            int bin = (int)(bits >> 12) - 0x3E800;
            bin = bin < 0 ? 0 : (bin > BINS - 1 ? BINS - 1 : bin);
            if (bin >= T) {
                int pos = atomicAdd(&sCnt, 1);
                if (pos < CAP)
                    sKeys[pos] = ((unsigned long long)bits << 32)
                               | (unsigned long long)(0xFFFFFFFFu - (unsigned)n);
            }
        }
    }
    __syncthreads();

    int cnt = sCnt < CAP ? sCnt : CAP;

    // exact rank by counting greater keys (keys unique: idx in low bits)
    for (int myi = t; myi < cnt; myi += 1024) {
        unsigned long long mykey = sKeys[myi];
        int rank = 0;
        for (int i = 0; i < cnt; ++i) rank += (sKeys[i] > mykey) ? 1 : 0;

        if (rank < MAXC) {
            unsigned bits = (unsigned)(mykey >> 32);
            unsigned idx  = 0xFFFFFFFFu - (unsigned)(mykey & 0xFFFFFFFFu);

            const float* p = pred + ((size_t)b * NANCH + idx) * STRIDE;
            float x = __ldg(p + 0), y = __ldg(p + 1);
            float w = __ldg(p + 2), h = __ldg(p + 3);
            float hw = __fmul_rn(w, 0.5f), hh = __fmul_rn(h, 0.5f);
            float bx1 = __fsub_rn(x, hw), by1 = __fsub_rn(y, hh);
            float bx2 = __fadd_rn(x, hw), by2 = __fadd_rn(y, hh);
            int   cls = (int)g_cls[b * NANCH + idx];
            float off = __fmul_rn((float)cls, 4096.0f);
            float ox1 = __fadd_rn(bx1, off), oy1 = __fadd_rn(by1, off);
            float ox2 = __fadd_rn(bx2, off), oy2 = __fadd_rn(by2, off);
            float area = __fmul_rn(__fsub_rn(ox2, ox1), __fsub_rn(oy2, oy1));

            int o = b * MAXC + rank;
            g_cmeta[o] = cls;
            g_ox1[o] = ox1; g_oy1[o] = oy1; g_ox2[o] = ox2; g_oy2[o] = oy2;
            g_oar[o] = area;
            g_bx1[o] = bx1; g_by1[o] = by1; g_bx2[o] = bx2; g_by2[o] = by2;
            g_conf[o] = __uint_as_float(bits);
        }
    }
}

// ---------------- K3: per-(batch,class) greedy NMS (warp per class) ----------------
// Cross-class IoU is exactly 0 (class offsets are multiples of 4096, raw boxes
// in [-0.5, 1.5]) so the reference's global greedy loop decomposes by class.
__global__ void __launch_bounds__(256) k_nms(float* __restrict__ out)
{
    const int BLOCKS_PER_B = NCLS / CPB;            // 10
    int b    = blockIdx.x / BLOCKS_PER_B;
    int wrp  = threadIdx.x >> 5;
    int lane = threadIdx.x & 31;
    int c    = (blockIdx.x % BLOCKS_PER_B) * CPB + wrp;

    __shared__ int   sm[MAXC];
    __shared__ float sx1[MAXC], sy1[MAXC], sx2[MAXC], sy2[MAXC], sa[MAXC];
    __shared__ float kbx[CPB][KCAP][5];             // per-warp kept boxes

    for (int i = threadIdx.x; i < MAXC; i += 256) {
        int o = b * MAXC + i;
        sm[i]  = g_cmeta[o];
        sx1[i] = g_ox1[o]; sy1[i] = g_oy1[o];
        sx2[i] = g_ox2[o]; sy2[i] = g_oy2[o];
        sa[i]  = g_oar[o];
    }
    __syncthreads();

    int nk = 0;
    for (int chunk = 0; chunk < 32; ++chunk) {
        int r = chunk * 32 + lane;
        int m = (r < MAXC) ? sm[r] : -1;
        unsigned mask = __ballot_sync(0xffffffffu, m == c);
        int keptflag = 0;

        while (mask) {
            int li = __ffs(mask) - 1;
            mask &= mask - 1;
            int ri = chunk * 32 + li;
            float cx1 = sx1[ri], cy1 = sy1[ri];
            float cx2 = sx2[ri], cy2 = sy2[ri], ca = sa[ri];

            int sup = 0;
            for (int base = 0; base < nk; base += 32) {
                int kidx = base + lane;
                if (kidx < nk) {
                    const float* kb = kbx[wrp][kidx];
                    float ltx = fmaxf(kb[0], cx1);
                    float lty = fmaxf(kb[1], cy1);
                    float rbx = fminf(kb[2], cx2);
                    float rby = fminf(kb[3], cy2);
                    float ww  = fmaxf(__fsub_rn(rbx, ltx), 0.0f);
                    float hh  = fmaxf(__fsub_rn(rby, lty), 0.0f);
                    float inter = __fmul_rn(ww, hh);
                    float den = __fadd_rn(__fsub_rn(__fadd_rn(kb[4], ca), inter), 1e-7f);
                    float iou = __fdiv_rn(inter, den);
                    if (iou > IOU_T) sup = 1;
                }
            }
            unsigned supb = __ballot_sync(0xffffffffu, sup);
            if (!supb) {
                if (lane == 0 && nk < KCAP) {
                    float* kb = kbx[wrp][nk];
                    kb[0] = cx1; kb[1] = cy1; kb[2] = cx2; kb[3] = cy2; kb[4] = ca;
                }
                nk++;
                if (lane == li) keptflag = 1;
            }
        }

        // kept candidates write their output rows (everything else stays 0)
        if (keptflag) {
            int o = b * MAXC + r;
            float* row = out + (size_t)o * 6;
            row[0] = g_bx1[o]; row[1] = g_by1[o];
            row[2] = g_bx2[o]; row[3] = g_by2[o];
            row[4] = g_conf[o];
            row[5] = (float)c;
            out[(size_t)BATCH * MAXC * 6 + o] = 1.0f;
        }
    }
}

// ---------------- launch ----------------
extern "C" void kernel_launch(void* const* d_in, const int* in_sizes, int n_in,
                              void* d_out, int out_size)
{
    (void)in_sizes; (void)n_in;
    const float* pred = (const float*)d_in[0];
    float* out = (float*)d_out;

    int zn = out_size > BATCH * BINS ? out_size : BATCH * BINS;
    k_zero<<<(zn + 255) / 256, 256>>>(out, out_size);

    int totalThreads = BATCH * NANCH * 32;   // warp per anchor
    k_score<<<(totalThreads + 255) / 256, 256>>>(pred);

    k_select<<<BATCH, 1024>>>(pred);
    k_nms<<<BATCH * (NCLS / CPB), 256>>>(out);
}